// round 7
// baseline (speedup 1.0000x reference)
#include <cuda_runtime.h>

// ---------------------------------------------------------------------------
// VQEmbedding via tf32 mma.sync (HMMA) candidate pass + exact fp32 rescore.
// N=131072 pixels, D=64, K=1024 codes.
// Exact scoring (bit-matches reference):
//   G = seq fp32 FMA over d ; dist = rn( rn(S+T) - 2G ) ; argmin, low-idx ties
// Output layout (float32): [ out : 8388608 | loss : 1 | indices : 131072 ]
// ---------------------------------------------------------------------------

#define NUM_K 1024
#define D 64
#define TN 128
#define OUT_ELEMS 8388608
#define LOSS_OFF  8388608
#define IDX_OFF   8388609

// smem byte offsets
#define AO_OFF   0                       // float ao[64][132]   = 33792 B
#define BS_OFF   33792                   // 2 x float [64][132] = 67584 B
#define TS_OFF   101376                  // float [1024]        = 4096 B
#define SS_OFF   105472                  // float [128]
#define GMIN_OFF 105984                  // float [128]
#define CAND_OFF 106496                  // int [128][48]       = 24576 B
#define BKS_OFF  131072                  // int [128]
#define OVF_OFF  131584                  // char [128]
#define RED_OFF  131712                  // float [8]
#define SMEM_TOTAL 131776

__device__ __align__(16) float g_wT[D * NUM_K];   // w transposed [d][k]
__device__ __align__(16) float g_T[NUM_K];        // exact sum(w^2)
__device__ int g_Tmax_i = 0;
__device__ double g_loss_sum;

__device__ __forceinline__ unsigned s2u(const void* p) {
    unsigned a;
    asm("{ .reg .u64 t; cvta.to.shared.u64 t, %1; cvt.u32.u64 %0, t; }"
        : "=r"(a) : "l"(p));
    return a;
}

__device__ __forceinline__ void mma_tf32(float c[4],
                                         unsigned a0, unsigned a1,
                                         unsigned a2, unsigned a3,
                                         unsigned b0, unsigned b1) {
    asm("mma.sync.aligned.m16n8k8.row.col.f32.tf32.tf32.f32 "
        "{%0,%1,%2,%3}, {%4,%5,%6,%7}, {%8,%9}, {%0,%1,%2,%3};"
        : "+f"(c[0]), "+f"(c[1]), "+f"(c[2]), "+f"(c[3])
        : "r"(a0), "r"(a1), "r"(a2), "r"(a3), "r"(b0), "r"(b1));
}

// ---------------------------------------------------------------------------
// Prep: transpose w into g_wT, exact T_k = sum(w^2), Tmax, zero loss.
// ---------------------------------------------------------------------------
__global__ __launch_bounds__(256)
void vq_prep(const float* __restrict__ w) {
    __shared__ float s[64][65];
    const int t = threadIdx.x;
    const int kb = blockIdx.x * 64;
    if (blockIdx.x == 0 && t == 0) g_loss_sum = 0.0;
    {
        int k = t >> 2, dq = (t & 3) << 4;
        const float4* src = (const float4*)(w + (kb + k) * D + dq);
        float4 v0 = src[0], v1 = src[1], v2 = src[2], v3 = src[3];
        s[dq+ 0][k]=v0.x; s[dq+ 1][k]=v0.y; s[dq+ 2][k]=v0.z; s[dq+ 3][k]=v0.w;
        s[dq+ 4][k]=v1.x; s[dq+ 5][k]=v1.y; s[dq+ 6][k]=v1.z; s[dq+ 7][k]=v1.w;
        s[dq+ 8][k]=v2.x; s[dq+ 9][k]=v2.y; s[dq+10][k]=v2.z; s[dq+11][k]=v2.w;
        s[dq+12][k]=v3.x; s[dq+13][k]=v3.y; s[dq+14][k]=v3.z; s[dq+15][k]=v3.w;
    }
    __syncthreads();
    {
        int d = t >> 2, kq = (t & 3) << 4;
        float4* dst = (float4*)(g_wT + d * NUM_K + kb + kq);
        #pragma unroll
        for (int j = 0; j < 4; j++) {
            float4 o;
            o.x = s[d][kq + 4*j + 0]; o.y = s[d][kq + 4*j + 1];
            o.z = s[d][kq + 4*j + 2]; o.w = s[d][kq + 4*j + 3];
            dst[j] = o;
        }
    }
    if (t < 64) {
        float acc = 0.f;
        #pragma unroll
        for (int d = 0; d < D; d++) {
            float v = s[d][t];
            acc = __fadd_rn(acc, __fmul_rn(v, v));
        }
        g_T[kb + t] = acc;
        atomicMax(&g_Tmax_i, __float_as_int(acc));   // acc > 0
    }
}

// stage one 64(d) x 128(k) B slab (g_wT cols s*128..+128) into buffer buf
// 2048 16B chunks: row d = idx>>5 (32 chunks/row), chunk c = idx&31
__device__ __forceinline__ void stage_b(char* sm, int buf, int s, int tid) {
    float* dst = (float*)(sm + BS_OFF) + buf * (64 * 132);
    const float* src = g_wT + s * 128;
    #pragma unroll
    for (int i = 0; i < 8; i++) {
        int idx = tid + i * 256;          // 0..2047
        int d = idx >> 5, c = idx & 31;
        unsigned sa = s2u(dst + d * 132 + c * 4);
        asm volatile("cp.async.cg.shared.global [%0], [%1], 16;"
                     :: "r"(sa), "l"(src + d * 1024 + c * 4));
    }
    asm volatile("cp.async.commit_group;" ::: "memory");
}

// ---------------------------------------------------------------------------
extern __shared__ char smc[];

__global__ __launch_bounds__(256, 1)
void vq_main(const float* __restrict__ x, const float* __restrict__ w,
             float* __restrict__ out) {
    const int tid = threadIdx.x;
    const int lane = tid & 31, wid = tid >> 5;
    const int gid = lane >> 2, tg = lane & 3;
    const int mg = wid & 3, ng = wid >> 2;

    float* ao   = (float*)(smc + AO_OFF);
    float* tsp  = (float*)(smc + TS_OFF);
    float* Ssm  = (float*)(smc + SS_OFF);
    float* gmin = (float*)(smc + GMIN_OFF);
    int*   cand = (int*)(smc + CAND_OFF);
    int*   bks  = (int*)(smc + BKS_OFF);
    char*  ovf  = smc + OVF_OFF;
    float* red  = (float*)(smc + RED_OFF);

    const int n0 = blockIdx.x * TN;
    const int b  = n0 >> 12;
    const int hw0 = n0 & 4095;
    const float* xb = x + ((size_t)b << 18);

    stage_b(smc, 0, 0, tid);
    {   // Ts via cp.async
        unsigned sa = s2u(tsp + tid * 4);
        asm volatile("cp.async.cg.shared.global [%0], [%1], 16;"
                     :: "r"(sa), "l"(g_T + tid * 4));
        asm volatile("cp.async.commit_group;" ::: "memory");
    }
    for (int e = tid; e < TN * D; e += 256) {
        int d = e >> 7, n = e & 127;
        ao[d * 132 + n] = xb[(d << 12) + hw0 + n];
    }
    for (int i = tid; i < 128 * 48; i += 256) cand[i] = -1;
    if (tid < 128) { gmin[tid] = 1e30f; ovf[tid] = 0; }
    asm volatile("cp.async.wait_group 0;" ::: "memory");
    __syncthreads();

    if (tid < TN) {   // exact S_n, sequential d
        float s = 0.f;
        #pragma unroll
        for (int d = 0; d < D; d++) {
            float v = ao[d * 132 + tid];
            s = __fadd_rn(s, __fmul_rn(v, v));
        }
        Ssm[tid] = s;
    }
    __syncthreads();

    const float Tmax = __int_as_float(g_Tmax_i);
    float Sr[4], epsr[4], mloc[4];
    int rix[4], cnt[4];
    #pragma unroll
    for (int q = 0; q < 4; q++) {
        int msub = q >> 1, hf = q & 1;
        int r = mg * 32 + msub * 16 + hf * 8 + gid;
        rix[q] = r; Sr[q] = Ssm[r];
        epsr[q] = 0.015625f * sqrtf(Sr[q] * Tmax) + 1e-7f;  // >= 2x tf32 bound
        mloc[q] = 1e30f; cnt[q] = 0;
    }

    #pragma unroll 1
    for (int s = 0; s < 8; s++) {
        const float* Bw = (float*)(smc + BS_OFF) + (s & 1) * (64 * 132) + ng * 64;
        if (s < 7) stage_b(smc, (s + 1) & 1, s + 1, tid);

        float acc[2][8][4];
        #pragma unroll
        for (int m = 0; m < 2; m++)
            #pragma unroll
            for (int n = 0; n < 8; n++)
                #pragma unroll
                for (int c = 0; c < 4; c++) acc[m][n][c] = 0.f;

        #pragma unroll
        for (int ks = 0; ks < 8; ks++) {
            const int dk = ks * 8 + tg;
            unsigned A0[2], A1[2], A2[2], A3[2];
            #pragma unroll
            for (int m = 0; m < 2; m++) {
                int rA = mg * 32 + m * 16 + gid;
                A0[m] = __float_as_uint(ao[dk * 132 + rA]);
                A1[m] = __float_as_uint(ao[dk * 132 + rA + 8]);
                A2[m] = __float_as_uint(ao[(dk + 4) * 132 + rA]);
                A3[m] = __float_as_uint(ao[(dk + 4) * 132 + rA + 8]);
            }
            #pragma unroll
            for (int ns = 0; ns < 8; ns++) {
                unsigned b0 = __float_as_uint(Bw[dk * 132 + ns * 8 + gid]);
                unsigned b1 = __float_as_uint(Bw[(dk + 4) * 132 + ns * 8 + gid]);
                mma_tf32(acc[0][ns], A0[0], A1[0], A2[0], A3[0], b0, b1);
                mma_tf32(acc[1][ns], A0[1], A1[1], A2[1], A3[1], b0, b1);
            }
        }

        // approximate scoring + guarded candidate capture
        const int k0 = s * 128 + ng * 64;
        float T16[16];
        #pragma unroll
        for (int ns = 0; ns < 8; ns++) {
            T16[ns * 2]     = tsp[k0 + ns * 8 + 2 * tg];
            T16[ns * 2 + 1] = tsp[k0 + ns * 8 + 2 * tg + 1];
        }
        #pragma unroll
        for (int q = 0; q < 4; q++) {
            int msub = q >> 1, hf = q & 1;
            float dv[16];
            float b16 = 1e30f;
            #pragma unroll
            for (int ns = 0; ns < 8; ns++) {
                float g0 = acc[msub][ns][hf * 2 + 0];
                float g1 = acc[msub][ns][hf * 2 + 1];
                float d0 = __fmaf_rn(-2.f, g0, __fadd_rn(Sr[q], T16[ns * 2]));
                float d1 = __fmaf_rn(-2.f, g1, __fadd_rn(Sr[q], T16[ns * 2 + 1]));
                dv[ns * 2] = d0; dv[ns * 2 + 1] = d1;
                b16 = fminf(b16, fminf(d0, d1));
            }
            float mr = fminf(mloc[q], gmin[rix[q]]);
            if (b16 < mr + epsr[q]) {
                float thr = fminf(mr, b16) + epsr[q];
                #pragma unroll
                for (int j = 0; j < 16; j++) {
                    if (dv[j] < thr) {
                        int k = k0 + (j >> 1) * 8 + 2 * tg + (j & 1);
                        if (cnt[q] < 6)
                            cand[rix[q] * 48 + (ng * 4 + tg) * 6 + cnt[q]] = k;
                        else
                            ovf[rix[q]] = 1;
                        cnt[q]++;
                    }
                }
                if (b16 < mloc[q]) mloc[q] = b16;
                if (b16 < mr)
                    atomicMin((int*)&gmin[rix[q]], __float_as_int(b16));
            }
        }

        if (s < 7) asm volatile("cp.async.wait_group 0;" ::: "memory");
        __syncthreads();
    }

    // pass 2: exact fp32 rescore (identical chain to reference)
    if (tid < TN) {
        const int p = tid;
        float xr[64];
        #pragma unroll
        for (int d = 0; d < D; d++) xr[d] = ao[d * 132 + p];
        const float Sp = Ssm[p];
        float bd = 1e30f; int bk = 0;
        if (ovf[p]) {
            #pragma unroll 1
            for (int k = 0; k < NUM_K; k++) {
                const float4* wr = (const float4*)(w + (k << 6));
                float G = 0.f;
                #pragma unroll
                for (int qd = 0; qd < 16; qd++) {
                    float4 wv = wr[qd];
                    G = __fmaf_rn(xr[qd*4+0], wv.x, G);
                    G = __fmaf_rn(xr[qd*4+1], wv.y, G);
                    G = __fmaf_rn(xr[qd*4+2], wv.z, G);
                    G = __fmaf_rn(xr[qd*4+3], wv.w, G);
                }
                float dvx = __fmaf_rn(-2.f, G, __fadd_rn(Sp, tsp[k]));
                if (dvx < bd || (dvx == bd && k < bk)) { bd = dvx; bk = k; }
            }
        } else {
            #pragma unroll 1
            for (int sl = 0; sl < 48; sl++) {
                int k = cand[p * 48 + sl];
                if (k < 0) continue;
                const float4* wr = (const float4*)(w + (k << 6));
                float G = 0.f;
                #pragma unroll
                for (int qd = 0; qd < 16; qd++) {
                    float4 wv = wr[qd];
                    G = __fmaf_rn(xr[qd*4+0], wv.x, G);
                    G = __fmaf_rn(xr[qd*4+1], wv.y, G);
                    G = __fmaf_rn(xr[qd*4+2], wv.z, G);
                    G = __fmaf_rn(xr[qd*4+3], wv.w, G);
                }
                float dvx = __fmaf_rn(-2.f, G, __fadd_rn(Sp, tsp[k]));
                if (dvx < bd || (dvx == bd && k < bk)) { bd = dvx; bk = k; }
            }
        }
        bks[p] = bk;
    }
    __syncthreads();

    // gather chosen codewords into B region for coalesced NCHW scatter
    float* wout = (float*)(smc + BS_OFF);
    if (tid < TN) {
        int k = bks[tid];
        const float4* src = (const float4*)(w + (k << 6));
        #pragma unroll
        for (int qd = 0; qd < 16; qd++) {
            float4 v = src[qd];
            int d0 = qd * 4;
            wout[(d0 + 0) * 132 + tid] = v.x;
            wout[(d0 + 1) * 132 + tid] = v.y;
            wout[(d0 + 2) * 132 + tid] = v.z;
            wout[(d0 + 3) * 132 + tid] = v.w;
        }
    }
    __syncthreads();

    const size_t ob = ((size_t)b << 18);
    float lsum = 0.f;
    for (int e = tid; e < TN * D; e += 256) {
        int d = e >> 7, n = e & 127;
        float wv = wout[d * 132 + n];
        float xv = ao[d * 132 + n];
        out[ob + (d << 12) + hw0 + n] = wv;
        float df = xv - wv;
        lsum += df * df;
    }
    if (tid < TN) out[IDX_OFF + n0 + tid] = (float)bks[tid];

    #pragma unroll
    for (int off = 16; off; off >>= 1)
        lsum += __shfl_xor_sync(0xffffffffu, lsum, off);
    if ((tid & 31) == 0) red[wid] = lsum;
    __syncthreads();
    if (tid == 0) {
        float s = 0.f;
        #pragma unroll
        for (int i = 0; i < 8; i++) s += red[i];
        atomicAdd(&g_loss_sum, (double)s);
    }
}

__global__ void vq_fin(float* __restrict__ out) {
    if (threadIdx.x == 0)
        out[LOSS_OFF] = (float)(1.25 * g_loss_sum / (double)OUT_ELEMS);
}

// ---------------------------------------------------------------------------
extern "C" void kernel_launch(void* const* d_in, const int* in_sizes, int n_in,
                              void* d_out, int out_size) {
    const float* x = (const float*)d_in[0];   // [32,64,64,64] f32
    const float* w = (const float*)d_in[1];   // [1024,64] f32
    float* out = (float*)d_out;

    cudaFuncSetAttribute(vq_main, cudaFuncAttributeMaxDynamicSharedMemorySize,
                         SMEM_TOTAL);
    vq_prep<<<16, 256>>>(w);
    vq_main<<<1024, 256, SMEM_TOTAL>>>(x, w, out);
    vq_fin<<<1, 32>>>(out);
}

// round 8
// speedup vs baseline: 1.2503x; 1.2503x over previous
#include <cuda_runtime.h>
#include <cuda_fp16.h>

// ---------------------------------------------------------------------------
// VQEmbedding via fp16 mma.sync m16n8k16 candidate pass + exact fp32 rescore.
// N=131072 pixels, D=64, K=1024 codes.
// Exact scoring (bit-matches reference):
//   G = seq fp32 FMA over d ; dist = rn( rn(S+T) - 2G ) ; argmin, low-idx ties
// Output layout (float32): [ out : 8388608 | loss : 1 | indices : 131072 ]
// ---------------------------------------------------------------------------

#define NUM_K 1024
#define D 64
#define TN 128
#define OUT_ELEMS 8388608
#define LOSS_OFF  8388608
#define IDX_OFF   8388609

// smem byte offsets
#define AF_OFF   0                  // float Af[128][68]          = 34816
#define ASH_OFF  34816              // half  Ash[128][72]         = 18432
#define BS_OFF   53248              // half  2 x [128][72]        = 36864
#define TS_OFF   90112              // float [1024]               = 4096
#define SS_OFF   94208              // float [128]
#define GMIN_OFF 94720              // float [128]
#define CAND_OFF 95232              // int [128][49]              = 25088
#define BKS_OFF  120320             // int [128]
#define OVF_OFF  120832             // char [128]
#define RED_OFF  120960             // float [8]
#define SMEM_TOTAL 120992

__device__ __align__(16) __half g_wh[NUM_K * D];  // fp16 codebook [k][d]
__device__ __align__(16) float  g_T[NUM_K];       // exact sum(w^2)
__device__ int g_Tmax_i = 0;
__device__ double g_loss_sum;

__device__ __forceinline__ unsigned s2u(const void* p) {
    unsigned a;
    asm("{ .reg .u64 t; cvta.to.shared.u64 t, %1; cvt.u32.u64 %0, t; }"
        : "=r"(a) : "l"(p));
    return a;
}

__device__ __forceinline__ void mma_f16(float c[4],
                                        unsigned a0, unsigned a1,
                                        unsigned a2, unsigned a3,
                                        unsigned b0, unsigned b1) {
    asm("mma.sync.aligned.m16n8k16.row.col.f32.f16.f16.f32 "
        "{%0,%1,%2,%3}, {%4,%5,%6,%7}, {%8,%9}, {%0,%1,%2,%3};"
        : "+f"(c[0]), "+f"(c[1]), "+f"(c[2]), "+f"(c[3])
        : "r"(a0), "r"(a1), "r"(a2), "r"(a3), "r"(b0), "r"(b1));
}

// ---------------------------------------------------------------------------
// Prep: fp16-convert w, exact T_k = sum(w^2), Tmax, zero loss.
// ---------------------------------------------------------------------------
__global__ __launch_bounds__(256)
void vq_prep(const float* __restrict__ w) {
    int t = blockIdx.x * 256 + threadIdx.x;        // 65536 threads
    if (t == 0) g_loss_sum = 0.0;
    if (t < NUM_K * D) g_wh[t] = __float2half_rn(w[t]);
    if (t < NUM_K) {
        const float* r = w + t * D;
        float s = 0.f;
        #pragma unroll
        for (int d = 0; d < D; d++)
            s = __fadd_rn(s, __fmul_rn(r[d], r[d]));
        g_T[t] = s;
        atomicMax(&g_Tmax_i, __float_as_int(s));   // s > 0
    }
}

// stage one 128(code) x 64(d) half slab into buffer buf (row stride 72 halves)
__device__ __forceinline__ void stage_b(char* sm, int buf, int s, int tid) {
    __half* dst = (__half*)(sm + BS_OFF) + buf * (128 * 72);
    const __half* src = g_wh + s * 128 * 64;
    #pragma unroll
    for (int i = 0; i < 4; i++) {
        int idx = tid + i * 256;                   // 0..1023 (16B chunks)
        int r = idx >> 3, c = idx & 7;
        unsigned sa = s2u(dst + r * 72 + c * 8);
        asm volatile("cp.async.cg.shared.global [%0], [%1], 16;"
                     :: "r"(sa), "l"(src + r * 64 + c * 8));
    }
    asm volatile("cp.async.commit_group;" ::: "memory");
}

// ---------------------------------------------------------------------------
extern __shared__ char smc[];

__global__ __launch_bounds__(256, 1)
void vq_main(const float* __restrict__ x, const float* __restrict__ w,
             float* __restrict__ out) {
    const int tid = threadIdx.x;
    const int lane = tid & 31, wid = tid >> 5;
    const int gid = lane >> 2, tg = lane & 3;
    const int mg = wid & 3, ng = wid >> 2;

    float*  Af   = (float*)(smc + AF_OFF);        // [n][68] fp32
    __half* Ash  = (__half*)(smc + ASH_OFF);      // [n][72] fp16
    float*  tsp  = (float*)(smc + TS_OFF);
    float*  Ssm  = (float*)(smc + SS_OFF);
    float*  gmin = (float*)(smc + GMIN_OFF);
    int*    cand = (int*)(smc + CAND_OFF);        // [128][49]
    int*    bks  = (int*)(smc + BKS_OFF);
    char*   ovf  = smc + OVF_OFF;
    float*  red  = (float*)(smc + RED_OFF);

    const int n0 = blockIdx.x * TN;
    const int b  = n0 >> 12;
    const int hw0 = n0 & 4095;
    const float* xb = x + ((size_t)b << 18);

    stage_b(smc, 0, 0, tid);
    {   // Ts via cp.async (1024 floats = 256 x 16B)
        unsigned sa = s2u(tsp + tid * 4);
        asm volatile("cp.async.cg.shared.global [%0], [%1], 16;"
                     :: "r"(sa), "l"(g_T + tid * 4));
        asm volatile("cp.async.commit_group;" ::: "memory");
    }
    // load x: fp32 copy (pixel-major) + fp16 operand copy
    #pragma unroll
    for (int i = 0; i < 32; i++) {
        int e = tid + i * 256;
        int d = e >> 7, n = e & 127;
        float v = xb[(d << 12) + hw0 + n];
        Af[n * 68 + d] = v;
        Ash[n * 72 + d] = __float2half_rn(v);
    }
    for (int i = tid; i < 128 * 49; i += 256) cand[i] = -1;
    if (tid < 128) { gmin[tid] = 1e30f; ovf[tid] = 0; }
    asm volatile("cp.async.wait_group 0;" ::: "memory");
    __syncthreads();

    if (tid < TN) {   // exact S_n, sequential d
        const float* r = Af + tid * 68;
        float s = 0.f;
        #pragma unroll
        for (int d = 0; d < D; d++)
            s = __fadd_rn(s, __fmul_rn(r[d], r[d]));
        Ssm[tid] = s;
    }
    __syncthreads();

    const float Tmax = __int_as_float(g_Tmax_i);
    float Sr[4], epsr[4], mloc[4];
    int rix[4], cnt[4];
    #pragma unroll
    for (int q = 0; q < 4; q++) {
        int msub = q >> 1, hf = q & 1;
        int r = mg * 32 + msub * 16 + hf * 8 + gid;
        rix[q] = r; Sr[q] = Ssm[r];
        epsr[q] = 0.00390625f * sqrtf(Sr[q] * Tmax) + 1e-5f;  // >= 2x fp16 bnd
        mloc[q] = 1e30f; cnt[q] = 0;
    }

    // hoist A fragments (chunk-invariant): 32 uints
    unsigned ua[2][4][4];
    #pragma unroll
    for (int m = 0; m < 2; m++) {
        int rb = mg * 32 + m * 16 + gid;
        #pragma unroll
        for (int ks = 0; ks < 4; ks++) {
            int k0 = ks * 16 + 2 * tg;
            ua[m][ks][0] = *(const unsigned*)(Ash + rb * 72 + k0);
            ua[m][ks][1] = *(const unsigned*)(Ash + (rb + 8) * 72 + k0);
            ua[m][ks][2] = *(const unsigned*)(Ash + rb * 72 + k0 + 8);
            ua[m][ks][3] = *(const unsigned*)(Ash + (rb + 8) * 72 + k0 + 8);
        }
    }

    #pragma unroll 1
    for (int s = 0; s < 8; s++) {
        const __half* Bp = (__half*)(smc + BS_OFF) + (s & 1) * (128 * 72);
        if (s < 7) stage_b(smc, (s + 1) & 1, s + 1, tid);

        float acc[2][8][4];
        #pragma unroll
        for (int m = 0; m < 2; m++)
            #pragma unroll
            for (int n = 0; n < 8; n++)
                #pragma unroll
                for (int c = 0; c < 4; c++) acc[m][n][c] = 0.f;

        #pragma unroll
        for (int ks = 0; ks < 4; ks++) {
            const int kk = ks * 16 + 2 * tg;
            #pragma unroll
            for (int ns = 0; ns < 8; ns++) {
                int rb = ng * 64 + ns * 8 + gid;
                unsigned b0 = *(const unsigned*)(Bp + rb * 72 + kk);
                unsigned b1 = *(const unsigned*)(Bp + rb * 72 + kk + 8);
                mma_f16(acc[0][ns], ua[0][ks][0], ua[0][ks][1],
                        ua[0][ks][2], ua[0][ks][3], b0, b1);
                mma_f16(acc[1][ns], ua[1][ks][0], ua[1][ks][1],
                        ua[1][ks][2], ua[1][ks][3], b0, b1);
            }
        }

        // approximate scoring + guarded candidate capture
        const int k0 = s * 128 + ng * 64;
        float T16[16];
        #pragma unroll
        for (int ns = 0; ns < 8; ns++) {
            T16[ns * 2]     = tsp[k0 + ns * 8 + 2 * tg];
            T16[ns * 2 + 1] = tsp[k0 + ns * 8 + 2 * tg + 1];
        }
        #pragma unroll
        for (int q = 0; q < 4; q++) {
            int msub = q >> 1, hf = q & 1;
            float dv[16];
            float b16 = 1e30f;
            #pragma unroll
            for (int ns = 0; ns < 8; ns++) {
                float g0 = acc[msub][ns][hf * 2 + 0];
                float g1 = acc[msub][ns][hf * 2 + 1];
                float d0 = __fmaf_rn(-2.f, g0, __fadd_rn(Sr[q], T16[ns * 2]));
                float d1 = __fmaf_rn(-2.f, g1, __fadd_rn(Sr[q], T16[ns * 2 + 1]));
                dv[ns * 2] = d0; dv[ns * 2 + 1] = d1;
                b16 = fminf(b16, fminf(d0, d1));
            }
            float mr = fminf(mloc[q], gmin[rix[q]]);
            if (b16 < mr + epsr[q]) {
                float thr = fminf(mr, b16) + epsr[q];
                #pragma unroll
                for (int j = 0; j < 16; j++) {
                    if (dv[j] < thr) {
                        int k = k0 + (j >> 1) * 8 + 2 * tg + (j & 1);
                        if (cnt[q] < 6)
                            cand[rix[q] * 49 + (ng * 4 + tg) * 6 + cnt[q]] = k;
                        else
                            ovf[rix[q]] = 1;
                        cnt[q]++;
                    }
                }
                if (b16 < mloc[q]) mloc[q] = b16;
                if (b16 < mr)
                    atomicMin((int*)&gmin[rix[q]], __float_as_int(b16));
            }
        }

        if (s < 7) asm volatile("cp.async.wait_group 0;" ::: "memory");
        __syncthreads();
    }

    // pass 2: exact fp32 rescore (identical chain to reference)
    if (tid < TN) {
        const int p = tid;
        float xr[64];
        const float4* ar = (const float4*)(Af + p * 68);
        #pragma unroll
        for (int qd = 0; qd < 16; qd++) {
            float4 v = ar[qd];
            xr[qd*4+0] = v.x; xr[qd*4+1] = v.y;
            xr[qd*4+2] = v.z; xr[qd*4+3] = v.w;
        }
        const float Sp = Ssm[p];
        float bd = 1e30f; int bk = 0;
        if (ovf[p]) {
            #pragma unroll 1
            for (int k = 0; k < NUM_K; k++) {
                const float4* wr = (const float4*)(w + (k << 6));
                float G = 0.f;
                #pragma unroll
                for (int qd = 0; qd < 16; qd++) {
                    float4 wv = wr[qd];
                    G = __fmaf_rn(xr[qd*4+0], wv.x, G);
                    G = __fmaf_rn(xr[qd*4+1], wv.y, G);
                    G = __fmaf_rn(xr[qd*4+2], wv.z, G);
                    G = __fmaf_rn(xr[qd*4+3], wv.w, G);
                }
                float dvx = __fmaf_rn(-2.f, G, __fadd_rn(Sp, tsp[k]));
                if (dvx < bd || (dvx == bd && k < bk)) { bd = dvx; bk = k; }
            }
        } else {
            #pragma unroll 1
            for (int sl = 0; sl < 48; sl++) {
                int k = cand[p * 49 + sl];
                if (k < 0) continue;
                const float4* wr = (const float4*)(w + (k << 6));
                float G = 0.f;
                #pragma unroll
                for (int qd = 0; qd < 16; qd++) {
                    float4 wv = wr[qd];
                    G = __fmaf_rn(xr[qd*4+0], wv.x, G);
                    G = __fmaf_rn(xr[qd*4+1], wv.y, G);
                    G = __fmaf_rn(xr[qd*4+2], wv.z, G);
                    G = __fmaf_rn(xr[qd*4+3], wv.w, G);
                }
                float dvx = __fmaf_rn(-2.f, G, __fadd_rn(Sp, tsp[k]));
                if (dvx < bd || (dvx == bd && k < bk)) { bd = dvx; bk = k; }
            }
        }
        bks[p] = bk;
    }
    __syncthreads();

    // gather chosen codewords into B region ([d][132]) for coalesced scatter
    float* wout = (float*)(smc + BS_OFF);
    if (tid < TN) {
        int k = bks[tid];
        const float4* src = (const float4*)(w + (k << 6));
        #pragma unroll
        for (int qd = 0; qd < 16; qd++) {
            float4 v = src[qd];
            int d0 = qd * 4;
            wout[(d0 + 0) * 132 + tid] = v.x;
            wout[(d0 + 1) * 132 + tid] = v.y;
            wout[(d0 + 2) * 132 + tid] = v.z;
            wout[(d0 + 3) * 132 + tid] = v.w;
        }
    }
    __syncthreads();

    const size_t ob = ((size_t)b << 18);
    float lsum = 0.f;
    #pragma unroll
    for (int i = 0; i < 32; i++) {
        int e = tid + i * 256;
        int d = e >> 7, n = e & 127;
        float wv = wout[d * 132 + n];
        float xv = Af[n * 68 + d];
        out[ob + (d << 12) + hw0 + n] = wv;
        float df = xv - wv;
        lsum += df * df;
    }
    if (tid < TN) out[IDX_OFF + n0 + tid] = (float)bks[tid];

    #pragma unroll
    for (int off = 16; off; off >>= 1)
        lsum += __shfl_xor_sync(0xffffffffu, lsum, off);
    if ((tid & 31) == 0) red[wid] = lsum;
    __syncthreads();
    if (tid == 0) {
        float s = 0.f;
        #pragma unroll
        for (int i = 0; i < 8; i++) s += red[i];
        atomicAdd(&g_loss_sum, (double)s);
    }
}

__global__ void vq_fin(float* __restrict__ out) {
    if (threadIdx.x == 0)
        out[LOSS_OFF] = (float)(1.25 * g_loss_sum / (double)OUT_ELEMS);
}

// ---------------------------------------------------------------------------
extern "C" void kernel_launch(void* const* d_in, const int* in_sizes, int n_in,
                              void* d_out, int out_size) {
    const float* x = (const float*)d_in[0];   // [32,64,64,64] f32
    const float* w = (const float*)d_in[1];   // [1024,64] f32
    float* out = (float*)d_out;

    cudaFuncSetAttribute(vq_main, cudaFuncAttributeMaxDynamicSharedMemorySize,
                         SMEM_TOTAL);
    vq_prep<<<256, 256>>>(w);
    vq_main<<<1024, 256, SMEM_TOTAL>>>(x, w, out);
    vq_fin<<<1, 32>>>(out);
}

// round 9
// speedup vs baseline: 1.9642x; 1.5710x over previous
#include <cuda_runtime.h>

// ---------------------------------------------------------------------------
// VQEmbedding, exact fp32 FFMA2 GEMM + argmin. Occ-2 edition (TK=64).
//   G_nk = seq fp32 FMA over d ; dist = rn( rn(S+T) - 2G ) ; argmin low-idx
// Output layout (float32): [ out : 8388608 | loss : 1 | indices : 131072 ]
// ---------------------------------------------------------------------------

#define TN 128
#define TK 64
#define APAD 132           // A row stride (floats)
#define WPAD 68            // W chunk row stride (floats)
#define NUM_K 1024
#define D 64
#define WOFF (D * WPAD)    // one W buffer, floats (4352)
#define OUT_ELEMS 8388608
#define LOSS_OFF  8388608
#define IDX_OFF   8388609

// smem float offsets
#define A_F    0                       // [64][132]      = 8448 floats
#define W_F    8448                    // 2 x [64][68]   = 8704
#define TS_F   17152                   // [1024]
#define SS_F   18176                   // [128]
#define BK_F   18304                   // [128] (ints)
#define RED_F  18432                   // [8]
#define SMEM_FLOATS 18440              // ~73.8 KB

__device__ __align__(16) float g_T[NUM_K];        // exact sum(w^2)
__device__ __align__(16) float g_wT[D * NUM_K];   // w transposed [d][k]
__device__ double g_loss_sum;

typedef unsigned long long ull;

__device__ __forceinline__ ull pack2(float x, float y) {
    ull r;
    asm("mov.b64 %0, {%1, %2};" : "=l"(r)
        : "r"(__float_as_uint(x)), "r"(__float_as_uint(y)));
    return r;
}
__device__ __forceinline__ void unpack2(ull p, float &x, float &y) {
    unsigned a, b;
    asm("mov.b64 {%0, %1}, %2;" : "=r"(a), "=r"(b) : "l"(p));
    x = __uint_as_float(a); y = __uint_as_float(b);
}
#define FMA2(d, a, b, c) \
    asm("fma.rn.f32x2 %0, %1, %2, %3;" : "=l"(d) : "l"(a), "l"(b), "l"(c))

// ---------------------------------------------------------------------------
// Prep: 16 blocks transpose w -> g_wT, exact T_k, zero loss.
// ---------------------------------------------------------------------------
__global__ __launch_bounds__(256)
void vq_prep(const float* __restrict__ w) {
    __shared__ float s[64][65];
    const int t = threadIdx.x;
    const int kb = blockIdx.x * 64;
    if (blockIdx.x == 0 && t == 0) g_loss_sum = 0.0;
    {
        int k = t >> 2, dq = (t & 3) << 4;
        const float4* src = (const float4*)(w + (kb + k) * D + dq);
        float4 v0 = src[0], v1 = src[1], v2 = src[2], v3 = src[3];
        s[dq+ 0][k]=v0.x; s[dq+ 1][k]=v0.y; s[dq+ 2][k]=v0.z; s[dq+ 3][k]=v0.w;
        s[dq+ 4][k]=v1.x; s[dq+ 5][k]=v1.y; s[dq+ 6][k]=v1.z; s[dq+ 7][k]=v1.w;
        s[dq+ 8][k]=v2.x; s[dq+ 9][k]=v2.y; s[dq+10][k]=v2.z; s[dq+11][k]=v2.w;
        s[dq+12][k]=v3.x; s[dq+13][k]=v3.y; s[dq+14][k]=v3.z; s[dq+15][k]=v3.w;
    }
    __syncthreads();
    {
        int d = t >> 2, kq = (t & 3) << 4;
        float4* dst = (float4*)(g_wT + d * NUM_K + kb + kq);
        #pragma unroll
        for (int j = 0; j < 4; j++) {
            float4 o;
            o.x = s[d][kq + 4*j + 0]; o.y = s[d][kq + 4*j + 1];
            o.z = s[d][kq + 4*j + 2]; o.w = s[d][kq + 4*j + 3];
            dst[j] = o;
        }
    }
    if (t < 64) {
        float acc = 0.f;
        #pragma unroll
        for (int d = 0; d < D; d++) {
            float v = s[d][t];
            acc = __fadd_rn(acc, __fmul_rn(v, v));
        }
        g_T[kb + t] = acc;
    }
}

// ---------------------------------------------------------------------------
__device__ __forceinline__ unsigned s2u(const void* p) {
    unsigned a;
    asm("{ .reg .u64 t; cvta.to.shared.u64 t, %1; cvt.u32.u64 %0, t; }"
        : "=r"(a) : "l"(p));
    return a;
}

// stage one 64(d) x 64(k) W chunk (g_wT cols c*64..) into buffer buf
__device__ __forceinline__ void stage_chunk(float* smf, int buf, int c, int tid) {
    float* dst = smf + W_F + buf * WOFF;
    const float* src = g_wT + c * TK;
    #pragma unroll
    for (int i = 0; i < 4; i++) {
        int idx = tid + i * 256;           // 0..1023 float4 chunks
        int d = idx >> 4, kk = (idx & 15) << 2;
        unsigned sa = s2u(dst + d * WPAD + kk);
        asm volatile("cp.async.cg.shared.global [%0], [%1], 16;"
                     :: "r"(sa), "l"(src + d * NUM_K + kk));
    }
    asm volatile("cp.async.commit_group;" ::: "memory");
}

extern __shared__ float smf[];

__global__ __launch_bounds__(256, 2)
void vq_main(const float* __restrict__ x, const float* __restrict__ w,
             float* __restrict__ out) {
    float* As  = smf + A_F;
    float* tsp = smf + TS_F;
    float* Ss  = smf + SS_F;
    int*   bks = (int*)(smf + BK_F);
    float* red = smf + RED_F;

    const int tid = threadIdx.x;
    const int tx = tid & 15;          // k: 4 codes
    const int ty = tid >> 4;          // n: 8 pixels
    const int n0 = blockIdx.x * TN;
    const int b  = n0 >> 12;
    const int hw0 = n0 & 4095;
    const float* xb = x + ((size_t)b << 18);

    // stage W chunk 0 + T table
    stage_chunk(smf, 0, 0, tid);
    {
        unsigned sa = s2u(tsp + tid * 4);
        asm volatile("cp.async.cg.shared.global [%0], [%1], 16;"
                     :: "r"(sa), "l"(g_T + tid * 4));
        asm volatile("cp.async.commit_group;" ::: "memory");
    }
    for (int e = tid; e < TN * D; e += 256) {
        int nl = e & 127, d = e >> 7;
        As[d * APAD + nl] = xb[(d << 12) + hw0 + nl];
    }
    asm volatile("cp.async.wait_group 0;" ::: "memory");
    __syncthreads();

    if (tid < TN) {                    // exact S_n, sequential d
        float s = 0.f;
        #pragma unroll
        for (int d = 0; d < D; d++) {
            float v = As[d * APAD + tid];
            s = __fadd_rn(s, __fmul_rn(v, v));
        }
        Ss[tid] = s;
    }
    __syncthreads();

    float s8[8];
    #pragma unroll
    for (int i = 0; i < 8; i++) s8[i] = Ss[(ty << 3) + i];

    float bestv[8];
    int   besti[8];
    #pragma unroll
    for (int i = 0; i < 8; i++) { bestv[i] = 3.4e38f; besti[i] = 0; }

    #pragma unroll 1
    for (int c = 0; c < 16; c++) {
        const int kc = c << 6;
        const float* cur = smf + W_F + (c & 1) * WOFF;
        if (c < 15) stage_chunk(smf, (c + 1) & 1, c + 1, tid);

        const int kb = kc + (tx << 2);
        float tk0 = tsp[kb], tk1 = tsp[kb + 1], tk2 = tsp[kb + 2], tk3 = tsp[kb + 3];

        ull acc[16];
        #pragma unroll
        for (int i = 0; i < 16; i++) acc[i] = 0ull;

        const float* Ar0 = As + (ty << 3);
        const float* Wr0 = cur + (tx << 2);
        #pragma unroll 8
        for (int d = 0; d < D; d++) {
            const float* Ar = Ar0 + d * APAD;
            const float* Wr = Wr0 + d * WPAD;
            ulonglong2 a01 = ((const ulonglong2*)Ar)[0];   // (n0,n1),(n2,n3)
            ulonglong2 a23 = ((const ulonglong2*)Ar)[1];   // (n4,n5),(n6,n7)
            float4 wv = *(const float4*)Wr;
            ull wd0 = pack2(wv.x, wv.x), wd1 = pack2(wv.y, wv.y);
            ull wd2 = pack2(wv.z, wv.z), wd3 = pack2(wv.w, wv.w);
            FMA2(acc[ 0], a01.x, wd0, acc[ 0]);
            FMA2(acc[ 1], a01.y, wd0, acc[ 1]);
            FMA2(acc[ 2], a23.x, wd0, acc[ 2]);
            FMA2(acc[ 3], a23.y, wd0, acc[ 3]);
            FMA2(acc[ 4], a01.x, wd1, acc[ 4]);
            FMA2(acc[ 5], a01.y, wd1, acc[ 5]);
            FMA2(acc[ 6], a23.x, wd1, acc[ 6]);
            FMA2(acc[ 7], a23.y, wd1, acc[ 7]);
            FMA2(acc[ 8], a01.x, wd2, acc[ 8]);
            FMA2(acc[ 9], a01.y, wd2, acc[ 9]);
            FMA2(acc[10], a23.x, wd2, acc[10]);
            FMA2(acc[11], a23.y, wd2, acc[11]);
            FMA2(acc[12], a01.x, wd3, acc[12]);
            FMA2(acc[13], a01.y, wd3, acc[13]);
            FMA2(acc[14], a23.x, wd3, acc[14]);
            FMA2(acc[15], a23.y, wd3, acc[15]);
        }

        // exact scoring: d = rn( rn(S+T) - 2G ); running argmin (low idx ties)
        float tkv[4] = {tk0, tk1, tk2, tk3};
        #pragma unroll
        for (int k = 0; k < 4; k++) {
            float T = tkv[k];
            int kg = kb + k;
            #pragma unroll
            for (int np = 0; np < 4; np++) {
                float G0, G1;
                unpack2(acc[k * 4 + np], G0, G1);
                float u0 = __fadd_rn(s8[2*np],     T);
                float u1 = __fadd_rn(s8[2*np + 1], T);
                float d0 = __fmaf_rn(-2.f, G0, u0);
                float d1 = __fmaf_rn(-2.f, G1, u1);
                if (d0 < bestv[2*np])     { bestv[2*np]     = d0; besti[2*np]     = kg; }
                if (d1 < bestv[2*np + 1]) { bestv[2*np + 1] = d1; besti[2*np + 1] = kg; }
            }
        }

        if (c < 15) { asm volatile("cp.async.wait_group 0;" ::: "memory"); }
        __syncthreads();
    }

    // reduce over the 16 tx lanes; smaller index wins exact ties
    #pragma unroll
    for (int i = 0; i < 8; i++) {
        float v = bestv[i]; int bi = besti[i];
        #pragma unroll
        for (int off = 8; off; off >>= 1) {
            float ov = __shfl_xor_sync(0xffffffffu, v, off);
            int   oi = __shfl_xor_sync(0xffffffffu, bi, off);
            if (ov < v || (ov == v && oi < bi)) { v = ov; bi = oi; }
        }
        if (tx == 0) bks[(ty << 3) + i] = bi;
    }
    __syncthreads();

    // gather chosen codewords into W region for coalesced NCHW scatter
    float* wout = smf + W_F;           // 8704 floats >= 64*132
    if (tid < TN) {
        int k = bks[tid];
        const float4* src = (const float4*)(w + (k << 6));
        #pragma unroll
        for (int j = 0; j < 16; j++) {
            float4 v = src[j];
            int d = j * 4;
            wout[(d + 0) * APAD + tid] = v.x;
            wout[(d + 1) * APAD + tid] = v.y;
            wout[(d + 2) * APAD + tid] = v.z;
            wout[(d + 3) * APAD + tid] = v.w;
        }
    }
    __syncthreads();

    const size_t ob = ((size_t)b << 18);
    float lsum = 0.f;
    for (int e = tid; e < TN * D; e += 256) {
        int nl = e & 127, d = e >> 7;
        float wv = wout[d * APAD + nl];
        float xv = As[d * APAD + nl];
        out[ob + (d << 12) + hw0 + nl] = wv;
        float df = xv - wv;
        lsum += df * df;
    }
    if (tid < TN) out[IDX_OFF + n0 + tid] = (float)bks[tid];

    #pragma unroll
    for (int off = 16; off; off >>= 1)
        lsum += __shfl_xor_sync(0xffffffffu, lsum, off);
    if ((tid & 31) == 0) red[tid >> 5] = lsum;
    __syncthreads();
    if (tid == 0) {
        float s = 0.f;
        #pragma unroll
        for (int i = 0; i < 8; i++) s += red[i];
        atomicAdd(&g_loss_sum, (double)s);
    }
}

__global__ void vq_fin(float* __restrict__ out) {
    if (threadIdx.x == 0)
        out[LOSS_OFF] = (float)(1.25 * g_loss_sum / (double)OUT_ELEMS);
}

// ---------------------------------------------------------------------------
extern "C" void kernel_launch(void* const* d_in, const int* in_sizes, int n_in,
                              void* d_out, int out_size) {
    const float* x = (const float*)d_in[0];   // [32,64,64,64] f32
    const float* w = (const float*)d_in[1];   // [1024,64] f32
    float* out = (float*)d_out;

    const int SMEM_BYTES = SMEM_FLOATS * 4;
    cudaFuncSetAttribute(vq_main, cudaFuncAttributeMaxDynamicSharedMemorySize,
                         SMEM_BYTES);

    vq_prep<<<16, 256>>>(w);
    vq_main<<<1024, 256, SMEM_BYTES>>>(x, w, out);
    vq_fin<<<1, 32>>>(out);
}